// round 4
// baseline (speedup 1.0000x reference)
#include <cuda_runtime.h>
#include <cuda_bf16.h>

// Problem constants (fixed by the dataset)
#define NN 50000
#define EE 800000
#define TOT_E (EE + NN)   // edges + self loops = 850000

// ---------------- scratch (no allocations allowed) ----------------
__device__ __align__(16) float g_C1[NN * 256];   // [xl1 | xr1] per node (128+128)
__device__ __align__(16) float g_h [NN * 128];   // layer-1 output after ELU
__device__ __align__(16) float g_C2[NN * 128];   // [xl2 | xr2] per node (64+64)
__device__ int   g_deg[NN];
__device__ int   g_tmp[NN];
__device__ int   g_off[NN + 1];
__device__ int   g_cur[NN];
__device__ int   g_bsum[64];
__device__ int   g_bscan[64];
__device__ int   g_csr[TOT_E];
__device__ int   g_is64;          // 1 if edge_index is int64, 0 if int32

// ---------------- edge-index dtype handling ----------------
__global__ void k_detect(const void* __restrict__ ei) {
    if (threadIdx.x == 0 && blockIdx.x == 0) {
        const long long* p = (const long long*)ei;
        int ok = 1;
        for (int i = 0; i < 64; i++) {
            long long v = p[i];
            if (v < 0 || v >= NN) { ok = 0; break; }
        }
        g_is64 = ok;
    }
}

__device__ __forceinline__ int edge_at(const void* ei, int idx) {
    // idx in [0, 2*EE): flat element index into edge_index
    if (g_is64) return (int)((const long long*)ei)[idx];
    return ((const int*)ei)[idx];
}

// ---------------- f32x2 packed math helpers ----------------
__device__ __forceinline__ unsigned long long pk2(float lo, float hi) {
    unsigned long long r;
    asm("mov.b64 %0, {%1, %2};" : "=l"(r) : "f"(lo), "f"(hi));
    return r;
}
__device__ __forceinline__ void fma2(unsigned long long& d, unsigned long long a, unsigned long long b) {
    asm("fma.rn.f32x2 %0, %1, %2, %3;" : "=l"(d) : "l"(a), "l"(b), "l"(d));
}
__device__ __forceinline__ float2 upk2(unsigned long long v) {
    float lo, hi;
    asm("mov.b64 {%0, %1}, %2;" : "=f"(lo), "=f"(hi) : "l"(v));
    return make_float2(lo, hi);
}

// ---------------- CSR build ----------------
__global__ void k_init_deg() {
    int i = blockIdx.x * blockDim.x + threadIdx.x;
    if (i < NN) g_deg[i] = 1;   // self loop
}

__global__ void k_hist(const void* __restrict__ ei) {
    int e = blockIdx.x * blockDim.x + threadIdx.x;
    if (e < EE) {
        int d = edge_at(ei, EE + e);
        atomicAdd(&g_deg[d], 1);
    }
}

__global__ void k_scan1() {
    __shared__ int sh[1024];
    int t = threadIdx.x;
    int i = blockIdx.x * 1024 + t;
    int v = (i < NN) ? g_deg[i] : 0;
    sh[t] = v;
    __syncthreads();
    #pragma unroll
    for (int off = 1; off < 1024; off <<= 1) {
        int x = (t >= off) ? sh[t - off] : 0;
        __syncthreads();
        sh[t] += x;
        __syncthreads();
    }
    if (i < NN) g_tmp[i] = sh[t] - v;          // exclusive within block
    if (t == 1023) g_bsum[blockIdx.x] = sh[1023];
}

__global__ void k_scan2(int nb) {
    if (threadIdx.x == 0 && blockIdx.x == 0) {
        int run = 0;
        for (int b = 0; b < nb; b++) { g_bscan[b] = run; run += g_bsum[b]; }
    }
}

__global__ void k_scan3() {
    int i = blockIdx.x * 1024 + threadIdx.x;
    if (i < NN) {
        int off = g_tmp[i] + g_bscan[blockIdx.x];
        g_off[i] = off;
        g_cur[i] = off;
        if (i == NN - 1) g_off[NN] = off + g_deg[i];
    }
}

__global__ void k_scatter(const void* __restrict__ ei) {
    int id = blockIdx.x * blockDim.x + threadIdx.x;
    if (id >= TOT_E) return;
    int s, d;
    if (id < EE) { s = edge_at(ei, id); d = edge_at(ei, EE + id); }
    else         { s = d = id - EE; }
    int p = atomicAdd(&g_cur[d], 1);
    g_csr[p] = s;
}

// ---------------- fp32 GEMM (f32x2 FFMA2), C[M x 2*split] = A[M x 128] @ [B0|B1] + [bias0|bias1]
// BM=128, BN=128, BK=16, 256 threads, per-thread 8x8 via packed f32x2.
// LAYER==1: A = x (param), C = g_C1, split=128. LAYER==2: A = g_h, C = g_C2, split=64.
template <int LAYER>
__global__ void __launch_bounds__(256, 2)
k_gemm(const float* __restrict__ Ain,
       const float* __restrict__ B0, const float* __restrict__ B1,
       const float* __restrict__ bias0, const float* __restrict__ bias1)
{
    __shared__ float As[16][132];   // transposed, padded
    __shared__ float Bs[16][128];

    const float* A = (LAYER == 1) ? Ain : g_h;
    float* C       = (LAYER == 1) ? g_C1 : g_C2;
    const int split = (LAYER == 1) ? 128 : 64;
    const int NB = 2 * split;
    const int M = NN;

    int tid = threadIdx.x;
    int tx = tid & 15, ty = tid >> 4;
    int rowBase = blockIdx.x * 128;
    int colBase = blockIdx.y * 128;

    unsigned long long acc[8][4];
    #pragma unroll
    for (int i = 0; i < 8; i++)
        #pragma unroll
        for (int j = 0; j < 4; j++) acc[i][j] = 0ull;

    for (int kb = 0; kb < 128; kb += 16) {
        // A tile: 128 rows x 16 k, stored transposed As[k][row]
        #pragma unroll
        for (int l = 0; l < 2; l++) {
            int fi = tid + l * 256;
            int arow = fi >> 2, kq = fi & 3;
            int grow = rowBase + arow;
            float4 v = make_float4(0.f, 0.f, 0.f, 0.f);
            if (grow < M) v = *(const float4*)&A[grow * 128 + kb + kq * 4];
            As[kq * 4 + 0][arow] = v.x;
            As[kq * 4 + 1][arow] = v.y;
            As[kq * 4 + 2][arow] = v.z;
            As[kq * 4 + 3][arow] = v.w;
        }
        // B tile: 16 k x 128 cols, sourced from B0 (col<split) or B1
        #pragma unroll
        for (int l = 0; l < 2; l++) {
            int fi = tid + l * 256;
            int brow = fi >> 5, cq = fi & 31;
            int gk = kb + brow;
            int gc = colBase + cq * 4;
            const float* Bp = (gc < split) ? &B0[gk * split + gc]
                                           : &B1[gk * split + gc - split];
            *(float4*)&Bs[brow][cq * 4] = *(const float4*)Bp;
        }
        __syncthreads();

        #pragma unroll
        for (int kk = 0; kk < 16; kk++) {
            float a[8], b[8];
            *(float4*)&a[0] = *(const float4*)&As[kk][ty * 8];
            *(float4*)&a[4] = *(const float4*)&As[kk][ty * 8 + 4];
            *(float4*)&b[0] = *(const float4*)&Bs[kk][tx * 4];
            *(float4*)&b[4] = *(const float4*)&Bs[kk][64 + tx * 4];
            unsigned long long bp[4];
            bp[0] = pk2(b[0], b[1]);
            bp[1] = pk2(b[2], b[3]);
            bp[2] = pk2(b[4], b[5]);
            bp[3] = pk2(b[6], b[7]);
            #pragma unroll
            for (int i = 0; i < 8; i++) {
                unsigned long long ap = pk2(a[i], a[i]);
                fma2(acc[i][0], ap, bp[0]);
                fma2(acc[i][1], ap, bp[1]);
                fma2(acc[i][2], ap, bp[2]);
                fma2(acc[i][3], ap, bp[3]);
            }
        }
        __syncthreads();
    }

    // epilogue: two float4 stores per row (cols tx*4 and 64+tx*4)
    #pragma unroll
    for (int i = 0; i < 8; i++) {
        int r = rowBase + ty * 8 + i;
        if (r >= M) continue;
        float2 v01 = upk2(acc[i][0]);
        float2 v23 = upk2(acc[i][1]);
        float2 v45 = upk2(acc[i][2]);
        float2 v67 = upk2(acc[i][3]);
        float o[8] = { v01.x, v01.y, v23.x, v23.y, v45.x, v45.y, v67.x, v67.y };
        #pragma unroll
        for (int half = 0; half < 2; half++) {
            int c0 = colBase + half * 64 + tx * 4;
            float4 w;
            float* wp = &w.x;
            #pragma unroll
            for (int jj = 0; jj < 4; jj++) {
                int c = c0 + jj;
                float bv = (c < split) ? bias0[c] : bias1[c - split];
                wp[jj] = o[half * 4 + jj] + bv;
            }
            *(float4*)&C[r * NB + c0] = w;
        }
    }
}

// ---------------- layer-1 edge pass: warp per node, 8 heads x 16 dims ----------------
// lane holds 4 contiguous dims [4*lane, 4*lane+4); head = lane>>2 (quad per head)
__global__ void __launch_bounds__(256)
k_edge1(const float* __restrict__ att1, const float* __restrict__ bias1)
{
    int warp = (blockIdx.x * blockDim.x + threadIdx.x) >> 5;
    int lane = threadIdx.x & 31;
    if (warp >= NN) return;
    int node = warp;
    int sub = lane & 3;
    int head = lane >> 2;

    float4 av = *(const float4*)&att1[head * 16 + sub * 4];
    float4 xr = *(const float4*)&g_C1[node * 256 + 128 + lane * 4];

    float m = -3.4e38f, s = 0.f;
    float4 acc = make_float4(0.f, 0.f, 0.f, 0.f);

    int beg = g_off[node], end = g_off[node + 1];
    for (int i = beg; i < end; i++) {
        int src = g_csr[i];
        float4 xl = *(const float4*)&g_C1[src * 256 + lane * 4];
        float tx0 = xl.x + xr.x, tx1 = xl.y + xr.y, tx2 = xl.z + xr.z, tx3 = xl.w + xr.w;
        tx0 = tx0 > 0.f ? tx0 : 0.2f * tx0;
        tx1 = tx1 > 0.f ? tx1 : 0.2f * tx1;
        tx2 = tx2 > 0.f ? tx2 : 0.2f * tx2;
        tx3 = tx3 > 0.f ? tx3 : 0.2f * tx3;
        float p = tx0 * av.x + tx1 * av.y + tx2 * av.z + tx3 * av.w;
        p += __shfl_xor_sync(0xffffffffu, p, 1);
        p += __shfl_xor_sync(0xffffffffu, p, 2);     // quad-wide alpha for this head
        float nm = fmaxf(m, p);
        float sc = __expf(m - nm);
        float w  = __expf(p - nm);
        s = s * sc + w;
        acc.x = acc.x * sc + w * xl.x;
        acc.y = acc.y * sc + w * xl.y;
        acc.z = acc.z * sc + w * xl.z;
        acc.w = acc.w * sc + w * xl.w;
        m = nm;
    }
    float inv = 1.f / s;
    float4 bv = *(const float4*)&bias1[lane * 4];
    float o0 = acc.x * inv + bv.x;
    float o1 = acc.y * inv + bv.y;
    float o2 = acc.z * inv + bv.z;
    float o3 = acc.w * inv + bv.w;
    // ELU
    o0 = o0 > 0.f ? o0 : expm1f(o0);
    o1 = o1 > 0.f ? o1 : expm1f(o1);
    o2 = o2 > 0.f ? o2 : expm1f(o2);
    o3 = o3 > 0.f ? o3 : expm1f(o3);
    *(float4*)&g_h[node * 128 + lane * 4] = make_float4(o0, o1, o2, o3);
}

// ---------------- layer-2 edge pass: warp per node, 1 head x 64 dims ----------------
// lane holds dims [2*lane, 2*lane+2)
__global__ void __launch_bounds__(256)
k_edge2(const float* __restrict__ att2, const float* __restrict__ bias2,
        float* __restrict__ out)
{
    int warp = (blockIdx.x * blockDim.x + threadIdx.x) >> 5;
    int lane = threadIdx.x & 31;
    if (warp >= NN) return;
    int node = warp;

    float2 av = *(const float2*)&att2[lane * 2];
    float2 xr = *(const float2*)&g_C2[node * 128 + 64 + lane * 2];

    float m = -3.4e38f, s = 0.f;
    float2 acc = make_float2(0.f, 0.f);

    int beg = g_off[node], end = g_off[node + 1];
    for (int i = beg; i < end; i++) {
        int src = g_csr[i];
        float2 xl = *(const float2*)&g_C2[src * 128 + lane * 2];
        float t0 = xl.x + xr.x, t1 = xl.y + xr.y;
        t0 = t0 > 0.f ? t0 : 0.2f * t0;
        t1 = t1 > 0.f ? t1 : 0.2f * t1;
        float p = t0 * av.x + t1 * av.y;
        p += __shfl_xor_sync(0xffffffffu, p, 1);
        p += __shfl_xor_sync(0xffffffffu, p, 2);
        p += __shfl_xor_sync(0xffffffffu, p, 4);
        p += __shfl_xor_sync(0xffffffffu, p, 8);
        p += __shfl_xor_sync(0xffffffffu, p, 16);    // warp-wide alpha
        float nm = fmaxf(m, p);
        float sc = __expf(m - nm);
        float w  = __expf(p - nm);
        s = s * sc + w;
        acc.x = acc.x * sc + w * xl.x;
        acc.y = acc.y * sc + w * xl.y;
        m = nm;
    }
    float inv = 1.f / s;
    float2 bv = *(const float2*)&bias2[lane * 2];
    float2 o;
    o.x = acc.x * inv + bv.x;
    o.y = acc.y * inv + bv.y;
    *(float2*)&out[node * 64 + lane * 2] = o;
}

// ---------------- launch ----------------
extern "C" void kernel_launch(void* const* d_in, const int* in_sizes, int n_in,
                              void* d_out, int out_size)
{
    const float* x     = (const float*)d_in[0];
    const void*  ei    = d_in[1];                  // int32 or int64, detected on device
    const float* W1l   = (const float*)d_in[2];
    const float* b1l   = (const float*)d_in[3];
    const float* W1r   = (const float*)d_in[4];
    const float* b1r   = (const float*)d_in[5];
    const float* att1  = (const float*)d_in[6];
    const float* bias1 = (const float*)d_in[7];
    const float* W2l   = (const float*)d_in[8];
    const float* b2l   = (const float*)d_in[9];
    const float* W2r   = (const float*)d_in[10];
    const float* b2r   = (const float*)d_in[11];
    const float* att2  = (const float*)d_in[12];
    const float* bias2 = (const float*)d_in[13];
    float* out = (float*)d_out;

    // CSR build
    k_detect<<<1, 32>>>(ei);
    k_init_deg<<<(NN + 255) / 256, 256>>>();
    k_hist<<<(EE + 255) / 256, 256>>>(ei);
    int nsb = (NN + 1023) / 1024;           // 49
    k_scan1<<<nsb, 1024>>>();
    k_scan2<<<1, 32>>>(nsb);
    k_scan3<<<nsb, 1024>>>();
    k_scatter<<<(TOT_E + 255) / 256, 256>>>(ei);

    // layer 1: C1 = [x@W1l + b1l | x@W1r + b1r]  (N x 256)
    {
        dim3 grid((NN + 127) / 128, 2);
        k_gemm<1><<<grid, 256>>>(x, W1l, W1r, b1l, b1r);
    }
    // layer-1 attention + aggregate + ELU -> g_h
    k_edge1<<<(NN * 32 + 255) / 256, 256>>>(att1, bias1);

    // layer 2: C2 = [h@W2l + b2l | h@W2r + b2r]  (N x 128)
    {
        dim3 grid((NN + 127) / 128, 1);
        k_gemm<2><<<grid, 256>>>(nullptr, W2l, W2r, b2l, b2r);
    }
    // layer-2 attention + aggregate -> out
    k_edge2<<<(NN * 32 + 255) / 256, 256>>>(att2, bias2, out);

    (void)in_sizes; (void)n_in; (void)out_size;
}